// round 11
// baseline (speedup 1.0000x reference)
#include <cuda_runtime.h>
#include <math.h>
#include <float.h>

#define NP    2048
#define MAXNP 256

// ---- shared memory layout (same as R9) ----
#define Q4_H1   0            // u4: [128 pts][20 u4]
#define H1Q 20
#define Q4_H2   2560         // placeholder start for H2 region expressed via h2sbase
#define H2Q 36
#define OFF_WH    38912
#define OFF_BH    40704
#define OFF_FEATS 40712
#define OFF_PTS   40968      // 768 raw point floats (16B aligned)
#define SMEM_FLOATS 41736    // 166,944 bytes

// H2 quad region actually lives at u4 [2560, 2560+128*36) like R6-R9:
// scalar store base = 4*Q4_H2 + ... ; loads use q4s[Q4_H2 + row*H2Q + ...]

extern __shared__ float s[];

__device__ unsigned g_ticket;
__global__ void reset_ticket_kernel() { g_ticket = 0u; }

__device__ __forceinline__ unsigned f2tf(float f) {
    unsigned u; asm("cvt.rna.tf32.f32 %0, %1;" : "=r"(u) : "f"(f)); return u;
}

__device__ __forceinline__ void mma8(float& c0, float& c1, float& c2, float& c3,
                                     unsigned a0, unsigned a1, unsigned a2, unsigned a3,
                                     unsigned b0, unsigned b1) {
    asm("mma.sync.aligned.m16n8k8.row.col.f32.tf32.tf32.f32 "
        "{%0,%1,%2,%3}, {%4,%5,%6,%7}, {%8,%9}, {%0,%1,%2,%3};"
        : "+f"(c0), "+f"(c1), "+f"(c2), "+f"(c3)
        : "r"(a0), "r"(a1), "r"(a2), "r"(a3), "r"(b0), "r"(b1));
}

__global__ __launch_bounds__(512, 1)
void refine_kernel(const float* __restrict__ points,
                   const int*   __restrict__ counts,
                   const float* __restrict__ proposals,
                   const float* __restrict__ W1, const float* __restrict__ b1,
                   const float* __restrict__ W2, const float* __restrict__ b2,
                   const float* __restrict__ W3, const float* __restrict__ b3,
                   const float* __restrict__ Wc, const float* __restrict__ bc,
                   const float* __restrict__ Wr, const float* __restrict__ br,
                   float* __restrict__ out)
{
    uint4*    q4s = (uint4*)s;
    unsigned* us  = (unsigned*)s;
    __shared__ unsigned s_pid[2];
    __shared__ float    s_prop[6];
    __shared__ int      s_ncnt;

    const int tid  = threadIdx.x;
    const int w    = tid >> 5;
    const int lane = tid & 31;
    const int g    = lane >> 2;
    const int tq   = lane & 3;

    // ---- stage W2^T quads into smem (tf32) ----
    for (int i = tid; i < 128 * 16; i += 512) {
        const int row = i >> 4, j = i & 15;
        const int sQ = j >> 2, tqQ = j & 3;
        const int k = 16 * sQ + tqQ;
        uint4 v;
        v.x = f2tf(W2[k * 128 + row]);
        v.y = f2tf(W2[(k + 4) * 128 + row]);
        v.z = f2tf(W2[(k + 8) * 128 + row]);
        v.w = f2tf(W2[(k + 12) * 128 + row]);
        q4s[10240 / 4 + row * 20 + j] = v;   // W2 quads at float 10240? -> use dedicated region below
    }
    // NOTE: W2 quad region: floats [OFF_W2F, OFF_W2F+10240) -- defined via constant:
    // (kept identical to R9's Q4_W2 region at u4 7168)
    __syncthreads();
    // Redo W2 staging into the canonical R9 region (u4 7168) to keep layout identical.
    for (int i = tid; i < 128 * 16; i += 512) {
        const int row = i >> 4, j = i & 15;
        const int sQ = j >> 2, tqQ = j & 3;
        const int k = 16 * sQ + tqQ;
        uint4 v;
        v.x = f2tf(W2[k * 128 + row]);
        v.y = f2tf(W2[(k + 4) * 128 + row]);
        v.z = f2tf(W2[(k + 8) * 128 + row]);
        v.w = f2tf(W2[(k + 12) * 128 + row]);
        q4s[7168 + row * 20 + j] = v;
    }
    if (tid < 256) {
        s[OFF_WH + tid] = Wc[tid];
        #pragma unroll
        for (int j = 0; j < 6; j++) s[OFF_WH + (1 + j) * 256 + tid] = Wr[tid * 6 + j];
    }
    if (tid == 0) s[OFF_BH] = bc[0];
    if (tid >= 1 && tid < 7) s[OFF_BH + tid] = br[tid - 1];

    const int chw = 16 * w;
    unsigned a3r[64];
    #pragma unroll
    for (int ks = 0; ks < 16; ks++) {
        const int k0 = 8 * ks;
        a3r[4 * ks + 0] = f2tf(W3[(k0 + tq)     * 256 + chw + g]);
        a3r[4 * ks + 1] = f2tf(W3[(k0 + tq)     * 256 + chw + g + 8]);
        a3r[4 * ks + 2] = f2tf(W3[(k0 + tq + 4) * 256 + chw + g]);
        a3r[4 * ks + 3] = f2tf(W3[(k0 + tq + 4) * 256 + chw + g + 8]);
    }

    const int wm  = w & 7;
    const int ch2 = 16 * wm + g;
    const float bb2a = b2[ch2];
    const float bb2b = b2[ch2 + 8];
    const float bb3a = b3[chw + g];
    const float bb3b = b3[chw + g + 8];
    const int l2half = w >> 3;
    const int h2sbase = 4 * Q4_H2 + wm * 16 + (g & 3) * 4 + (g >> 2);

    if (tid == 0) s_pid[0] = atomicAdd(&g_ticket, 1u);
    __syncthreads();

    {   // prologue: stage first proposal fully (fixed 192 u4 point row)
        const unsigned pid0 = s_pid[0];
        if (pid0 < NP) {
            if (tid == 0) s_ncnt = counts[pid0];
            if (tid >= 32 && tid < 38) s_prop[tid - 32] = proposals[pid0 * 6 + (tid - 32)];
            const uint4* gp4 = (const uint4*)(points + (size_t)pid0 * (MAXNP * 3));
            uint4* sp4 = (uint4*)(s + OFF_PTS);
            if (tid < 192) sp4[tid] = __ldg(gp4 + tid);
        }
    }
    __syncthreads();

    // layer-1 worker (constants passed explicitly so it can serve next proposal too)
    auto do_l1 = [&](float cen0, float cen1, float cen2,
                     float is0, float is1, float is2, int base, int cnt8) {
        for (int i = tid; i < cnt8 * 16; i += 512) {
            const int p = i >> 4, j = i & 15;
            const int sQ = j >> 2, tqQ = j & 3;
            const int c = 16 * sQ + tqQ;
            const float* pt = s + OFF_PTS + (base + p) * 3;
            const float x0 = (pt[0] - cen0) * is0;
            const float x1 = (pt[1] - cen1) * is1;
            const float x2 = (pt[2] - cen2) * is2;
            uint4 v;
            { float h = fmaf(x2, W1[128 + c], fmaf(x1, W1[64 + c], fmaf(x0, W1[c], b1[c])));
              v.x = f2tf(fmaxf(h, 0.0f)); }
            { float h = fmaf(x2, W1[128 + c + 4], fmaf(x1, W1[64 + c + 4], fmaf(x0, W1[c + 4], b1[c + 4])));
              v.y = f2tf(fmaxf(h, 0.0f)); }
            { float h = fmaf(x2, W1[128 + c + 8], fmaf(x1, W1[64 + c + 8], fmaf(x0, W1[c + 8], b1[c + 8])));
              v.z = f2tf(fmaxf(h, 0.0f)); }
            { float h = fmaf(x2, W1[128 + c + 12], fmaf(x1, W1[64 + c + 12], fmaf(x0, W1[c + 12], b1[c + 12])));
              v.w = f2tf(fmaxf(h, 0.0f)); }
            q4s[Q4_H1 + p * H1Q + j] = v;
        }
    };

    int par = 0;
    bool h1_ready = false;
    for (;;) {
        const unsigned pid = s_pid[par];
        if (pid >= NP) break;
        if (tid == 0) s_pid[par ^ 1] = atomicAdd(&g_ticket, 1u);
        const int n = s_ncnt;
        const bool valid = (n >= 4);

        float chmax0 = -FLT_MAX, chmax1 = -FLT_MAX;

        if (valid) {
            const float cen0 = s_prop[0], cen1 = s_prop[1], cen2 = s_prop[2];
            const float is0 = 1.0f / (fabsf(s_prop[3]) + 1e-6f);
            const float is1 = 1.0f / (fabsf(s_prop[4]) + 1e-6f);
            const float is2 = 1.0f / (fabsf(s_prop[5]) + 1e-6f);

            if (!h1_ready) {
                const int tp0 = min(128, n);
                do_l1(cen0, cen1, cen2, is0, is1, is2, 0, (tp0 + 7) & ~7);
                __syncthreads();
            }

            for (int p0b = 0; p0b < n; p0b += 128) {
                const int tp = min(128, n - p0b);
                const bool last_tile = (p0b + 128 >= n);

                // ---- layer 2 phase ----
                #pragma unroll
                for (int ng = 0; ng < 2; ng++) {
                    const int n0b = 64 * l2half + 32 * ng;
                    if (n0b < tp) {
                        const int ntmax = min(4, (tp - n0b + 7) >> 3);
                        float acc[4][4];
                        #pragma unroll
                        for (int nt = 0; nt < 4; nt++) {
                            acc[nt][0] = 0.f; acc[nt][1] = 0.f; acc[nt][2] = 0.f; acc[nt][3] = 0.f;
                        }
                        #pragma unroll
                        for (int sQ = 0; sQ < 4; sQ++) {
                            const uint4 aQ0 = q4s[7168 + (16 * wm + g)     * 20 + 4 * sQ + tq];
                            const uint4 aQ1 = q4s[7168 + (16 * wm + g + 8) * 20 + 4 * sQ + tq];
                            #pragma unroll
                            for (int nt = 0; nt < 4; nt++) {
                                if (nt < ntmax) {
                                    const uint4 bQ = q4s[Q4_H1 + (n0b + 8 * nt + g) * H1Q + 4 * sQ + tq];
                                    mma8(acc[nt][0], acc[nt][1], acc[nt][2], acc[nt][3],
                                         aQ0.x, aQ1.x, aQ0.y, aQ1.y, bQ.x, bQ.y);
                                    mma8(acc[nt][0], acc[nt][1], acc[nt][2], acc[nt][3],
                                         aQ0.z, aQ1.z, aQ0.w, aQ1.w, bQ.z, bQ.w);
                                }
                            }
                        }
                        #pragma unroll
                        for (int nt = 0; nt < 4; nt++) {
                            if (nt < ntmax) {
                                const int p0 = n0b + 8 * nt + 2 * tq;
                                const int b0 = h2sbase + p0 * 144;
                                us[b0]           = f2tf(fmaxf(acc[nt][0] + bb2a, 0.0f));
                                us[b0 + 144]     = f2tf(fmaxf(acc[nt][1] + bb2a, 0.0f));
                                us[b0 + 2]       = f2tf(fmaxf(acc[nt][2] + bb2b, 0.0f));
                                us[b0 + 2 + 144] = f2tf(fmaxf(acc[nt][3] + bb2b, 0.0f));
                            }
                        }
                    }
                }
                __syncthreads();

                // ---- layer 3 phase (+ staging of next proposal on last tile) ----
                unsigned npid = s_pid[par ^ 1];
                uint4  stg = make_uint4(0u, 0u, 0u, 0u);
                float  stgp = 0.0f;
                int    stgc = 0;
                const bool have_next = last_tile && (npid < NP);
                if (have_next) {
                    if (tid < 192) {
                        const uint4* gp4 = (const uint4*)(points + (size_t)npid * (MAXNP * 3));
                        stg = __ldg(gp4 + tid);
                    }
                    if (tid >= 198 && tid < 204) stgp = __ldg(proposals + (size_t)npid * 6 + (tid - 198));
                    if (tid == 204) stgc = __ldg(counts + npid);
                }

                #pragma unroll
                for (int ng = 0; ng < 4; ng++) {
                    const int n0 = 32 * ng;
                    if (n0 >= tp) break;
                    const int ntmax = min(4, (tp - n0 + 7) >> 3);
                    float acc[4][4];
                    #pragma unroll
                    for (int nt = 0; nt < 4; nt++) {
                        acc[nt][0] = 0.f; acc[nt][1] = 0.f; acc[nt][2] = 0.f; acc[nt][3] = 0.f;
                    }
                    // double-buffered B-fragment prefetch across sQ
                    uint4 bq[2][4];
                    #pragma unroll
                    for (int nt = 0; nt < 4; nt++)
                        if (nt < ntmax)
                            bq[0][nt] = q4s[Q4_H2 + (n0 + 8 * nt + g) * H2Q + tq];
                    #pragma unroll
                    for (int sQ = 0; sQ < 8; sQ++) {
                        const int cur = sQ & 1, nxt = cur ^ 1;
                        if (sQ < 7) {
                            #pragma unroll
                            for (int nt = 0; nt < 4; nt++)
                                if (nt < ntmax)
                                    bq[nxt][nt] = q4s[Q4_H2 + (n0 + 8 * nt + g) * H2Q + 4 * (sQ + 1) + tq];
                        }
                        #pragma unroll
                        for (int nt = 0; nt < 4; nt++) {
                            if (nt < ntmax) {
                                mma8(acc[nt][0], acc[nt][1], acc[nt][2], acc[nt][3],
                                     a3r[8 * sQ + 0], a3r[8 * sQ + 1], a3r[8 * sQ + 2], a3r[8 * sQ + 3],
                                     bq[cur][nt].x, bq[cur][nt].y);
                                mma8(acc[nt][0], acc[nt][1], acc[nt][2], acc[nt][3],
                                     a3r[8 * sQ + 4], a3r[8 * sQ + 5], a3r[8 * sQ + 6], a3r[8 * sQ + 7],
                                     bq[cur][nt].z, bq[cur][nt].w);
                            }
                        }
                    }
                    #pragma unroll
                    for (int nt = 0; nt < 4; nt++) {
                        const int p0 = n0 + 8 * nt + 2 * tq;
                        if (p0 < tp) {
                            chmax0 = fmaxf(chmax0, acc[nt][0]);
                            chmax1 = fmaxf(chmax1, acc[nt][2]);
                        }
                        if (p0 + 1 < tp) {
                            chmax0 = fmaxf(chmax0, acc[nt][1]);
                            chmax1 = fmaxf(chmax1, acc[nt][3]);
                        }
                    }
                }

                if (!last_tile) {
                    // fold L1 of tile 1 into this phase (T is at most 2)
                    const int tpn = min(128, n - p0b - 128);
                    do_l1(cen0, cen1, cen2, is0, is1, is2, p0b + 128, (tpn + 7) & ~7);
                    __syncthreads();
                } else if (have_next) {
                    // publish staged next-proposal data (LDG latency was hidden under mma)
                    uint4* sp4 = (uint4*)(s + OFF_PTS);
                    if (tid < 192) sp4[tid] = stg;
                    if (tid >= 198 && tid < 204) s_prop[tid - 198] = stgp;
                    if (tid == 204) s_ncnt = stgc;
                }
            }

            chmax0 = fmaxf(chmax0, __shfl_xor_sync(0xffffffffu, chmax0, 1));
            chmax0 = fmaxf(chmax0, __shfl_xor_sync(0xffffffffu, chmax0, 2));
            chmax1 = fmaxf(chmax1, __shfl_xor_sync(0xffffffffu, chmax1, 1));
            chmax1 = fmaxf(chmax1, __shfl_xor_sync(0xffffffffu, chmax1, 2));
            if (tq == 0) {
                s[OFF_FEATS + chw + g]     = chmax0 + bb3a;
                s[OFF_FEATS + chw + g + 8] = chmax1 + bb3b;
            }
        }

        __syncthreads();   // T1: feats + staged next data visible
        const unsigned npid2 = s_pid[par ^ 1];
        bool nvalid = false;
        int  nn = 0;
        if (valid && npid2 < NP) { nn = s_ncnt; nvalid = (nn >= 4); }

        if (w < 7) {
            if (valid) {
                float acc = 0.0f;
                #pragma unroll
                for (int i = 0; i < 8; i++) {
                    const int idx = i * 32 + lane;
                    acc = fmaf(s[OFF_FEATS + idx], s[OFF_WH + w * 256 + idx], acc);
                }
                #pragma unroll
                for (int o = 16; o > 0; o >>= 1)
                    acc += __shfl_xor_sync(0xffffffffu, acc, o);
                if (lane == 0) {
                    if (w == 0) out[pid] = acc + s[OFF_BH];
                    else        out[NP + pid * 6 + (w - 1)] = acc + s[OFF_BH + w];
                }
            } else if (lane == 0) {
                if (w == 0) out[pid] = s[OFF_BH];
                else        out[NP + pid * 6 + (w - 1)] = s[OFF_BH + w];
            }
        }

        if (!valid) {
            // invalid proposal: stage next the old way (rare path)
            if (w == 7) {
                if (npid2 < NP) {
                    if (lane < 6) s_prop[lane] = proposals[(size_t)npid2 * 6 + lane];
                    if (lane == 6) s_ncnt = counts[npid2];
                }
            } else if (w >= 8) {
                if (npid2 < NP) {
                    const uint4* gp4 = (const uint4*)(points + (size_t)npid2 * (MAXNP * 3));
                    uint4* sp4 = (uint4*)(s + OFF_PTS);
                    if (tid - 256 < 192) sp4[tid - 256] = __ldg(gp4 + (tid - 256));
                }
            }
            h1_ready = false;
        } else if (nvalid) {
            // all warps: layer-1 for next proposal's tile 0 (points/prop staged under L3)
            const float c0n = s_prop[0], c1n = s_prop[1], c2n = s_prop[2];
            const float i0n = 1.0f / (fabsf(s_prop[3]) + 1e-6f);
            const float i1n = 1.0f / (fabsf(s_prop[4]) + 1e-6f);
            const float i2n = 1.0f / (fabsf(s_prop[5]) + 1e-6f);
            const int tp0 = min(128, nn);
            do_l1(c0n, c1n, c2n, i0n, i1n, i2n, 0, (tp0 + 7) & ~7);
            h1_ready = true;
        } else {
            h1_ready = false;
        }
        __syncthreads();   // T2
        par ^= 1;
    }
}

extern "C" void kernel_launch(void* const* d_in, const int* in_sizes, int n_in,
                              void* d_out, int out_size)
{
    const float* points    = (const float*)d_in[0];
    const int*   counts    = (const int*)  d_in[1];
    const float* proposals = (const float*)d_in[2];
    const float* W1 = (const float*)d_in[3];
    const float* b1 = (const float*)d_in[4];
    const float* W2 = (const float*)d_in[5];
    const float* b2 = (const float*)d_in[6];
    const float* W3 = (const float*)d_in[7];
    const float* b3 = (const float*)d_in[8];
    const float* Wc = (const float*)d_in[9];
    const float* bc = (const float*)d_in[10];
    const float* Wr = (const float*)d_in[11];
    const float* br = (const float*)d_in[12];
    float* out = (float*)d_out;

    int dev = 0, sms = 148;
    cudaGetDevice(&dev);
    cudaDeviceGetAttribute(&sms, cudaDevAttrMultiProcessorCount, dev);
    cudaFuncSetAttribute(refine_kernel,
                         cudaFuncAttributeMaxDynamicSharedMemorySize,
                         SMEM_FLOATS * (int)sizeof(float));

    reset_ticket_kernel<<<1, 1>>>();
    refine_kernel<<<sms, 512, SMEM_FLOATS * (int)sizeof(float)>>>(
        points, counts, proposals, W1, b1, W2, b2, W3, b3, Wc, bc, Wr, br, out);
}

// round 12
// speedup vs baseline: 1.4552x; 1.4552x over previous
#include <cuda_runtime.h>
#include <math.h>
#include <float.h>

#define NP    2048
#define MAXNP 256

// ---- shared memory layout (R9) ----
#define Q4_H1   0            // u4: [128 pts][20 u4]
#define H1Q 20
#define Q4_H2   2560         // u4: [128 pts][36 u4]
#define H2Q 36
#define Q4_W2   7168         // u4: [128 ch][20 u4]
#define W2Q 20
#define OFF_WH    38912
#define OFF_BH    40704
#define OFF_FEATS 40712
#define OFF_PTS   40968      // 768 raw point floats (16B aligned)
#define SMEM_FLOATS 41736    // 166,944 bytes

extern __shared__ float s[];

__device__ unsigned g_ticket;
__global__ void reset_ticket_kernel() { g_ticket = 0u; }

__device__ __forceinline__ unsigned f2tf(float f) {
    unsigned u; asm("cvt.rna.tf32.f32 %0, %1;" : "=r"(u) : "f"(f)); return u;
}

__device__ __forceinline__ void mma8(float& c0, float& c1, float& c2, float& c3,
                                     unsigned a0, unsigned a1, unsigned a2, unsigned a3,
                                     unsigned b0, unsigned b1) {
    asm("mma.sync.aligned.m16n8k8.row.col.f32.tf32.tf32.f32 "
        "{%0,%1,%2,%3}, {%4,%5,%6,%7}, {%8,%9}, {%0,%1,%2,%3};"
        : "+f"(c0), "+f"(c1), "+f"(c2), "+f"(c3)
        : "r"(a0), "r"(a1), "r"(a2), "r"(a3), "r"(b0), "r"(b1));
}

__global__ __launch_bounds__(512, 1)
void refine_kernel(const float* __restrict__ points,
                   const int*   __restrict__ counts,
                   const float* __restrict__ proposals,
                   const float* __restrict__ W1, const float* __restrict__ b1,
                   const float* __restrict__ W2, const float* __restrict__ b2,
                   const float* __restrict__ W3, const float* __restrict__ b3,
                   const float* __restrict__ Wc, const float* __restrict__ bc,
                   const float* __restrict__ Wr, const float* __restrict__ br,
                   float* __restrict__ out)
{
    uint4*    q4s = (uint4*)s;
    unsigned* us  = (unsigned*)s;
    __shared__ unsigned s_pid[2];
    __shared__ float    s_prop[6];
    __shared__ int      s_ncnt;

    const int tid  = threadIdx.x;
    const int w    = tid >> 5;
    const int lane = tid & 31;
    const int g    = lane >> 2;
    const int tq   = lane & 3;

    // ---- stage W2^T quads into smem (tf32) ----
    for (int i = tid; i < 128 * 16; i += 512) {
        const int row = i >> 4, j = i & 15;
        const int sQ = j >> 2, tqQ = j & 3;
        const int k = 16 * sQ + tqQ;
        uint4 v;
        v.x = f2tf(W2[k * 128 + row]);
        v.y = f2tf(W2[(k + 4) * 128 + row]);
        v.z = f2tf(W2[(k + 8) * 128 + row]);
        v.w = f2tf(W2[(k + 12) * 128 + row]);
        q4s[Q4_W2 + row * W2Q + j] = v;
    }
    if (tid < 256) {
        s[OFF_WH + tid] = Wc[tid];
        #pragma unroll
        for (int j = 0; j < 6; j++) s[OFF_WH + (1 + j) * 256 + tid] = Wr[tid * 6 + j];
    }
    if (tid == 0) s[OFF_BH] = bc[0];
    if (tid >= 1 && tid < 7) s[OFF_BH + tid] = br[tid - 1];

    const int chw = 16 * w;
    unsigned a3r[64];
    #pragma unroll
    for (int ks = 0; ks < 16; ks++) {
        const int k0 = 8 * ks;
        a3r[4 * ks + 0] = f2tf(W3[(k0 + tq)     * 256 + chw + g]);
        a3r[4 * ks + 1] = f2tf(W3[(k0 + tq)     * 256 + chw + g + 8]);
        a3r[4 * ks + 2] = f2tf(W3[(k0 + tq + 4) * 256 + chw + g]);
        a3r[4 * ks + 3] = f2tf(W3[(k0 + tq + 4) * 256 + chw + g + 8]);
    }

    const int wm  = w & 7;
    const int ch2 = 16 * wm + g;
    const float bb2a = b2[ch2];
    const float bb2b = b2[ch2 + 8];
    const float bb3a = b3[chw + g];
    const float bb3b = b3[chw + g + 8];
    const int l2half = w >> 3;
    const int h2sbase = 4 * Q4_H2 + wm * 16 + (g & 3) * 4 + (g >> 2);

    if (tid == 0) s_pid[0] = atomicAdd(&g_ticket, 1u);
    __syncthreads();

    {   // prologue: stage first proposal
        const unsigned pid0 = s_pid[0];
        if (pid0 < NP) {
            const int nn = counts[pid0];
            if (tid == 0) s_ncnt = nn;
            if (tid >= 32 && tid < 38) s_prop[tid - 32] = proposals[pid0 * 6 + (tid - 32)];
            const uint4* gp4 = (const uint4*)(points + (size_t)pid0 * (MAXNP * 3));
            uint4* sp4 = (uint4*)(s + OFF_PTS);
            const int nf4 = (3 * nn + 3) >> 2;
            for (int i = tid; i < nf4; i += 512) sp4[i] = __ldg(gp4 + i);
        }
    }
    __syncthreads();

    // layer-1 worker with explicit proposal constants
    auto do_l1 = [&](float cen0, float cen1, float cen2,
                     float is0, float is1, float is2, int base, int cnt8) {
        for (int i = tid; i < cnt8 * 16; i += 512) {
            const int p = i >> 4, j = i & 15;
            const int sQ = j >> 2, tqQ = j & 3;
            const int c = 16 * sQ + tqQ;
            const float* pt = s + OFF_PTS + (base + p) * 3;
            const float x0 = (pt[0] - cen0) * is0;
            const float x1 = (pt[1] - cen1) * is1;
            const float x2 = (pt[2] - cen2) * is2;
            uint4 v;
            { float h = fmaf(x2, W1[128 + c], fmaf(x1, W1[64 + c], fmaf(x0, W1[c], b1[c])));
              v.x = f2tf(fmaxf(h, 0.0f)); }
            { float h = fmaf(x2, W1[128 + c + 4], fmaf(x1, W1[64 + c + 4], fmaf(x0, W1[c + 4], b1[c + 4])));
              v.y = f2tf(fmaxf(h, 0.0f)); }
            { float h = fmaf(x2, W1[128 + c + 8], fmaf(x1, W1[64 + c + 8], fmaf(x0, W1[c + 8], b1[c + 8])));
              v.z = f2tf(fmaxf(h, 0.0f)); }
            { float h = fmaf(x2, W1[128 + c + 12], fmaf(x1, W1[64 + c + 12], fmaf(x0, W1[c + 12], b1[c + 12])));
              v.w = f2tf(fmaxf(h, 0.0f)); }
            q4s[Q4_H1 + p * H1Q + j] = v;
        }
    };

    int par = 0;
    bool h1_ready = false;
    for (;;) {
        const unsigned pid = s_pid[par];
        if (pid >= NP) break;
        if (tid == 0) s_pid[par ^ 1] = atomicAdd(&g_ticket, 1u);
        const int n = s_ncnt;
        const bool valid = (n >= 4);

        float chmax0 = -FLT_MAX, chmax1 = -FLT_MAX;

        if (valid) {
            const float cen0 = s_prop[0], cen1 = s_prop[1], cen2 = s_prop[2];
            const float is0 = 1.0f / (fabsf(s_prop[3]) + 1e-6f);
            const float is1 = 1.0f / (fabsf(s_prop[4]) + 1e-6f);
            const float is2 = 1.0f / (fabsf(s_prop[5]) + 1e-6f);

            if (!h1_ready) {
                const int tp0 = min(128, n);
                do_l1(cen0, cen1, cen2, is0, is1, is2, 0, (tp0 + 7) & ~7);
                __syncthreads();
            }

            for (int p0b = 0; p0b < n; p0b += 128) {
                const int tp = min(128, n - p0b);

                // ---- layer 2 (R9 form: aQ from smem, single-buffer bQ) ----
                #pragma unroll
                for (int ng = 0; ng < 2; ng++) {
                    const int n0b = 64 * l2half + 32 * ng;
                    if (n0b < tp) {
                        const int ntmax = min(4, (tp - n0b + 7) >> 3);
                        float acc[4][4];
                        #pragma unroll
                        for (int nt = 0; nt < 4; nt++) {
                            acc[nt][0] = 0.f; acc[nt][1] = 0.f; acc[nt][2] = 0.f; acc[nt][3] = 0.f;
                        }
                        #pragma unroll
                        for (int sQ = 0; sQ < 4; sQ++) {
                            const uint4 aQ0 = q4s[Q4_W2 + (16 * wm + g)     * W2Q + 4 * sQ + tq];
                            const uint4 aQ1 = q4s[Q4_W2 + (16 * wm + g + 8) * W2Q + 4 * sQ + tq];
                            #pragma unroll
                            for (int nt = 0; nt < 4; nt++) {
                                if (nt < ntmax) {
                                    const uint4 bQ = q4s[Q4_H1 + (n0b + 8 * nt + g) * H1Q + 4 * sQ + tq];
                                    mma8(acc[nt][0], acc[nt][1], acc[nt][2], acc[nt][3],
                                         aQ0.x, aQ1.x, aQ0.y, aQ1.y, bQ.x, bQ.y);
                                    mma8(acc[nt][0], acc[nt][1], acc[nt][2], acc[nt][3],
                                         aQ0.z, aQ1.z, aQ0.w, aQ1.w, bQ.z, bQ.w);
                                }
                            }
                        }
                        #pragma unroll
                        for (int nt = 0; nt < 4; nt++) {
                            if (nt < ntmax) {
                                const int p0 = n0b + 8 * nt + 2 * tq;
                                const int b0 = h2sbase + p0 * 144;
                                us[b0]           = f2tf(fmaxf(acc[nt][0] + bb2a, 0.0f));
                                us[b0 + 144]     = f2tf(fmaxf(acc[nt][1] + bb2a, 0.0f));
                                us[b0 + 2]       = f2tf(fmaxf(acc[nt][2] + bb2b, 0.0f));
                                us[b0 + 2 + 144] = f2tf(fmaxf(acc[nt][3] + bb2b, 0.0f));
                            }
                        }
                    }
                }
                __syncthreads();

                // ---- layer 3 (R9 form) + lookahead L1 of tile 1 ----
                #pragma unroll
                for (int ng = 0; ng < 4; ng++) {
                    const int n0 = 32 * ng;
                    if (n0 >= tp) break;
                    const int ntmax = min(4, (tp - n0 + 7) >> 3);
                    float acc[4][4];
                    #pragma unroll
                    for (int nt = 0; nt < 4; nt++) {
                        acc[nt][0] = 0.f; acc[nt][1] = 0.f; acc[nt][2] = 0.f; acc[nt][3] = 0.f;
                    }
                    #pragma unroll
                    for (int sQ = 0; sQ < 8; sQ++) {
                        #pragma unroll
                        for (int nt = 0; nt < 4; nt++) {
                            if (nt < ntmax) {
                                const uint4 bQ = q4s[Q4_H2 + (n0 + 8 * nt + g) * H2Q + 4 * sQ + tq];
                                mma8(acc[nt][0], acc[nt][1], acc[nt][2], acc[nt][3],
                                     a3r[8 * sQ + 0], a3r[8 * sQ + 1], a3r[8 * sQ + 2], a3r[8 * sQ + 3],
                                     bQ.x, bQ.y);
                                mma8(acc[nt][0], acc[nt][1], acc[nt][2], acc[nt][3],
                                     a3r[8 * sQ + 4], a3r[8 * sQ + 5], a3r[8 * sQ + 6], a3r[8 * sQ + 7],
                                     bQ.z, bQ.w);
                            }
                        }
                    }
                    #pragma unroll
                    for (int nt = 0; nt < 4; nt++) {
                        const int p0 = n0 + 8 * nt + 2 * tq;
                        if (p0 < tp) {
                            chmax0 = fmaxf(chmax0, acc[nt][0]);
                            chmax1 = fmaxf(chmax1, acc[nt][2]);
                        }
                        if (p0 + 1 < tp) {
                            chmax0 = fmaxf(chmax0, acc[nt][1]);
                            chmax1 = fmaxf(chmax1, acc[nt][3]);
                        }
                    }
                }
                if (p0b + 128 < n) {
                    const int tpn = min(128, n - p0b - 128);
                    do_l1(cen0, cen1, cen2, is0, is1, is2, p0b + 128, (tpn + 7) & ~7);
                    __syncthreads();
                }
            }

            chmax0 = fmaxf(chmax0, __shfl_xor_sync(0xffffffffu, chmax0, 1));
            chmax0 = fmaxf(chmax0, __shfl_xor_sync(0xffffffffu, chmax0, 2));
            chmax1 = fmaxf(chmax1, __shfl_xor_sync(0xffffffffu, chmax1, 1));
            chmax1 = fmaxf(chmax1, __shfl_xor_sync(0xffffffffu, chmax1, 2));
            if (tq == 0) {
                s[OFF_FEATS + chw + g]     = chmax0 + bb3a;
                s[OFF_FEATS + chw + g + 8] = chmax1 + bb3b;
            }
        }

        __syncthreads();   // T1: feats ready; s_pid[par^1] published; H1 free
        const unsigned npid = s_pid[par ^ 1];

        // tail: heads (w<7) || prop/count staging (w==7) || point staging (w>=8)
        if (w < 7) {
            if (valid) {
                float acc = 0.0f;
                #pragma unroll
                for (int i = 0; i < 8; i++) {
                    const int idx = i * 32 + lane;
                    acc = fmaf(s[OFF_FEATS + idx], s[OFF_WH + w * 256 + idx], acc);
                }
                #pragma unroll
                for (int o = 16; o > 0; o >>= 1)
                    acc += __shfl_xor_sync(0xffffffffu, acc, o);
                if (lane == 0) {
                    if (w == 0) out[pid] = acc + s[OFF_BH];
                    else        out[NP + pid * 6 + (w - 1)] = acc + s[OFF_BH + w];
                }
            } else if (lane == 0) {
                if (w == 0) out[pid] = s[OFF_BH];
                else        out[NP + pid * 6 + (w - 1)] = s[OFF_BH + w];
            }
        } else if (w == 7) {
            if (npid < NP) {
                if (lane < 6) s_prop[lane] = proposals[(size_t)npid * 6 + lane];
                if (lane == 6) s_ncnt = counts[npid];
            }
        } else {
            if (npid < NP) {
                const int nn = counts[npid];
                const uint4* gp4 = (const uint4*)(points + (size_t)npid * (MAXNP * 3));
                uint4* sp4 = (uint4*)(s + OFF_PTS);
                const int nf4 = (3 * nn + 3) >> 2;
                for (int i = tid - 256; i < nf4; i += 256) sp4[i] = __ldg(gp4 + i);
            }
        }
        __syncthreads();   // T1.5: next points + prop + count staged

        // hidden L1: all warps compute next proposal's tile-0 H1
        if (npid < NP) {
            const int nn = s_ncnt;
            if (nn >= 4) {
                const float c0n = s_prop[0], c1n = s_prop[1], c2n = s_prop[2];
                const float i0n = 1.0f / (fabsf(s_prop[3]) + 1e-6f);
                const float i1n = 1.0f / (fabsf(s_prop[4]) + 1e-6f);
                const float i2n = 1.0f / (fabsf(s_prop[5]) + 1e-6f);
                const int tp0 = min(128, nn);
                do_l1(c0n, c1n, c2n, i0n, i1n, i2n, 0, (tp0 + 7) & ~7);
                h1_ready = true;
            } else {
                h1_ready = false;
            }
        } else {
            h1_ready = false;
        }
        __syncthreads();   // T2: H1(next) ready
        par ^= 1;
    }
}

extern "C" void kernel_launch(void* const* d_in, const int* in_sizes, int n_in,
                              void* d_out, int out_size)
{
    const float* points    = (const float*)d_in[0];
    const int*   counts    = (const int*)  d_in[1];
    const float* proposals = (const float*)d_in[2];
    const float* W1 = (const float*)d_in[3];
    const float* b1 = (const float*)d_in[4];
    const float* W2 = (const float*)d_in[5];
    const float* b2 = (const float*)d_in[6];
    const float* W3 = (const float*)d_in[7];
    const float* b3 = (const float*)d_in[8];
    const float* Wc = (const float*)d_in[9];
    const float* bc = (const float*)d_in[10];
    const float* Wr = (const float*)d_in[11];
    const float* br = (const float*)d_in[12];
    float* out = (float*)d_out;

    int dev = 0, sms = 148;
    cudaGetDevice(&dev);
    cudaDeviceGetAttribute(&sms, cudaDevAttrMultiProcessorCount, dev);
    cudaFuncSetAttribute(refine_kernel,
                         cudaFuncAttributeMaxDynamicSharedMemorySize,
                         SMEM_FLOATS * (int)sizeof(float));

    reset_ticket_kernel<<<1, 1>>>();
    refine_kernel<<<sms, 512, SMEM_FLOATS * (int)sizeof(float)>>>(
        points, counts, proposals, W1, b1, W2, b2, W3, b3, Wc, bc, Wr, br, out);
}

// round 13
// speedup vs baseline: 1.4590x; 1.0026x over previous
#include <cuda_runtime.h>
#include <math.h>
#include <float.h>

#define NP    2048
#define MAXNP 256

// ---- shared memory layout (R9) ----
#define Q4_H1   0            // u4: [128 pts][20 u4]
#define H1Q 20
#define Q4_H2   2560         // u4: [128 pts][36 u4]
#define H2Q 36
#define Q4_W2   7168         // u4: [128 ch][20 u4]
#define W2Q 20
#define OFF_WH    38912
#define OFF_BH    40704
#define OFF_FEATS 40712
#define OFF_PTS   40968      // 768 raw point floats (16B aligned)
#define SMEM_FLOATS 41736    // 166,944 bytes

extern __shared__ float s[];

__device__ unsigned g_ticket;
__global__ void reset_ticket_kernel() { g_ticket = 0u; }

__device__ __forceinline__ unsigned f2tf(float f) {
    unsigned u; asm("cvt.rna.tf32.f32 %0, %1;" : "=r"(u) : "f"(f)); return u;
}

__device__ __forceinline__ void mma8(float& c0, float& c1, float& c2, float& c3,
                                     unsigned a0, unsigned a1, unsigned a2, unsigned a3,
                                     unsigned b0, unsigned b1) {
    asm("mma.sync.aligned.m16n8k8.row.col.f32.tf32.tf32.f32 "
        "{%0,%1,%2,%3}, {%4,%5,%6,%7}, {%8,%9}, {%0,%1,%2,%3};"
        : "+f"(c0), "+f"(c1), "+f"(c2), "+f"(c3)
        : "r"(a0), "r"(a1), "r"(a2), "r"(a3), "r"(b0), "r"(b1));
}

__global__ __launch_bounds__(512, 1)
void refine_kernel(const float* __restrict__ points,
                   const int*   __restrict__ counts,
                   const float* __restrict__ proposals,
                   const float* __restrict__ W1, const float* __restrict__ b1,
                   const float* __restrict__ W2, const float* __restrict__ b2,
                   const float* __restrict__ W3, const float* __restrict__ b3,
                   const float* __restrict__ Wc, const float* __restrict__ bc,
                   const float* __restrict__ Wr, const float* __restrict__ br,
                   float* __restrict__ out)
{
    uint4*    q4s = (uint4*)s;
    unsigned* us  = (unsigned*)s;
    __shared__ unsigned s_pid[2];
    __shared__ float    s_prop[6];
    __shared__ int      s_ncnt;

    const int tid  = threadIdx.x;
    const int w    = tid >> 5;
    const int lane = tid & 31;
    const int g    = lane >> 2;
    const int tq   = lane & 3;

    // ---- stage W2^T quads into smem (tf32) ----
    for (int i = tid; i < 128 * 16; i += 512) {
        const int row = i >> 4, j = i & 15;
        const int sQ = j >> 2, tqQ = j & 3;
        const int k = 16 * sQ + tqQ;
        uint4 v;
        v.x = f2tf(W2[k * 128 + row]);
        v.y = f2tf(W2[(k + 4) * 128 + row]);
        v.z = f2tf(W2[(k + 8) * 128 + row]);
        v.w = f2tf(W2[(k + 12) * 128 + row]);
        q4s[Q4_W2 + row * W2Q + j] = v;
    }
    if (tid < 256) {
        s[OFF_WH + tid] = Wc[tid];
        #pragma unroll
        for (int j = 0; j < 6; j++) s[OFF_WH + (1 + j) * 256 + tid] = Wr[tid * 6 + j];
    }
    if (tid == 0) s[OFF_BH] = bc[0];
    if (tid >= 1 && tid < 7) s[OFF_BH + tid] = br[tid - 1];

    const int chw = 16 * w;
    unsigned a3r[64];
    #pragma unroll
    for (int ks = 0; ks < 16; ks++) {
        const int k0 = 8 * ks;
        a3r[4 * ks + 0] = f2tf(W3[(k0 + tq)     * 256 + chw + g]);
        a3r[4 * ks + 1] = f2tf(W3[(k0 + tq)     * 256 + chw + g + 8]);
        a3r[4 * ks + 2] = f2tf(W3[(k0 + tq + 4) * 256 + chw + g]);
        a3r[4 * ks + 3] = f2tf(W3[(k0 + tq + 4) * 256 + chw + g + 8]);
    }

    const int wm  = w & 7;
    const int ch2 = 16 * wm + g;
    const float bb2a = b2[ch2];
    const float bb2b = b2[ch2 + 8];
    const float bb3a = b3[chw + g];
    const float bb3b = b3[chw + g + 8];
    const int l2half = w >> 3;
    const int h2sbase = 4 * Q4_H2 + wm * 16 + (g & 3) * 4 + (g >> 2);

    if (tid == 0) s_pid[0] = atomicAdd(&g_ticket, 1u);
    __syncthreads();

    {   // prologue: stage first proposal
        const unsigned pid0 = s_pid[0];
        if (pid0 < NP) {
            const int nn = counts[pid0];
            if (tid == 0) s_ncnt = nn;
            if (tid >= 32 && tid < 38) s_prop[tid - 32] = proposals[pid0 * 6 + (tid - 32)];
            const uint4* gp4 = (const uint4*)(points + (size_t)pid0 * (MAXNP * 3));
            uint4* sp4 = (uint4*)(s + OFF_PTS);
            const int nf4 = (3 * nn + 3) >> 2;
            for (int i = tid; i < nf4; i += 512) sp4[i] = __ldg(gp4 + i);
        }
    }
    __syncthreads();

    // layer-1 worker with explicit proposal constants
    auto do_l1 = [&](float cen0, float cen1, float cen2,
                     float is0, float is1, float is2, int base, int cnt8) {
        for (int i = tid; i < cnt8 * 16; i += 512) {
            const int p = i >> 4, j = i & 15;
            const int sQ = j >> 2, tqQ = j & 3;
            const int c = 16 * sQ + tqQ;
            const float* pt = s + OFF_PTS + (base + p) * 3;
            const float x0 = (pt[0] - cen0) * is0;
            const float x1 = (pt[1] - cen1) * is1;
            const float x2 = (pt[2] - cen2) * is2;
            uint4 v;
            { float h = fmaf(x2, W1[128 + c], fmaf(x1, W1[64 + c], fmaf(x0, W1[c], b1[c])));
              v.x = f2tf(fmaxf(h, 0.0f)); }
            { float h = fmaf(x2, W1[128 + c + 4], fmaf(x1, W1[64 + c + 4], fmaf(x0, W1[c + 4], b1[c + 4])));
              v.y = f2tf(fmaxf(h, 0.0f)); }
            { float h = fmaf(x2, W1[128 + c + 8], fmaf(x1, W1[64 + c + 8], fmaf(x0, W1[c + 8], b1[c + 8])));
              v.z = f2tf(fmaxf(h, 0.0f)); }
            { float h = fmaf(x2, W1[128 + c + 12], fmaf(x1, W1[64 + c + 12], fmaf(x0, W1[c + 12], b1[c + 12])));
              v.w = f2tf(fmaxf(h, 0.0f)); }
            q4s[Q4_H1 + p * H1Q + j] = v;
        }
    };

    int par = 0;
    bool h1_ready = false;
    for (;;) {
        const unsigned pid = s_pid[par];
        if (pid >= NP) break;
        if (tid == 0) s_pid[par ^ 1] = atomicAdd(&g_ticket, 1u);
        const int n = s_ncnt;
        const bool valid = (n >= 4);

        float chmax0 = -FLT_MAX, chmax1 = -FLT_MAX;

        if (valid) {
            const float cen0 = s_prop[0], cen1 = s_prop[1], cen2 = s_prop[2];
            const float is0 = 1.0f / (fabsf(s_prop[3]) + 1e-6f);
            const float is1 = 1.0f / (fabsf(s_prop[4]) + 1e-6f);
            const float is2 = 1.0f / (fabsf(s_prop[5]) + 1e-6f);

            if (!h1_ready) {
                const int tp0 = min(128, n);
                do_l1(cen0, cen1, cen2, is0, is1, is2, 0, (tp0 + 7) & ~7);
                __syncthreads();
            }

            for (int p0b = 0; p0b < n; p0b += 128) {
                const int tp = min(128, n - p0b);

                // ---- layer 2 (R9 form: aQ from smem, single-buffer bQ) ----
                #pragma unroll
                for (int ng = 0; ng < 2; ng++) {
                    const int n0b = 64 * l2half + 32 * ng;
                    if (n0b < tp) {
                        const int ntmax = min(4, (tp - n0b + 7) >> 3);
                        float acc[4][4];
                        #pragma unroll
                        for (int nt = 0; nt < 4; nt++) {
                            acc[nt][0] = 0.f; acc[nt][1] = 0.f; acc[nt][2] = 0.f; acc[nt][3] = 0.f;
                        }
                        #pragma unroll
                        for (int sQ = 0; sQ < 4; sQ++) {
                            const uint4 aQ0 = q4s[Q4_W2 + (16 * wm + g)     * W2Q + 4 * sQ + tq];
                            const uint4 aQ1 = q4s[Q4_W2 + (16 * wm + g + 8) * W2Q + 4 * sQ + tq];
                            #pragma unroll
                            for (int nt = 0; nt < 4; nt++) {
                                if (nt < ntmax) {
                                    const uint4 bQ = q4s[Q4_H1 + (n0b + 8 * nt + g) * H1Q + 4 * sQ + tq];
                                    mma8(acc[nt][0], acc[nt][1], acc[nt][2], acc[nt][3],
                                         aQ0.x, aQ1.x, aQ0.y, aQ1.y, bQ.x, bQ.y);
                                    mma8(acc[nt][0], acc[nt][1], acc[nt][2], acc[nt][3],
                                         aQ0.z, aQ1.z, aQ0.w, aQ1.w, bQ.z, bQ.w);
                                }
                            }
                        }
                        #pragma unroll
                        for (int nt = 0; nt < 4; nt++) {
                            if (nt < ntmax) {
                                const int p0 = n0b + 8 * nt + 2 * tq;
                                const int b0 = h2sbase + p0 * 144;
                                us[b0]           = f2tf(fmaxf(acc[nt][0] + bb2a, 0.0f));
                                us[b0 + 144]     = f2tf(fmaxf(acc[nt][1] + bb2a, 0.0f));
                                us[b0 + 2]       = f2tf(fmaxf(acc[nt][2] + bb2b, 0.0f));
                                us[b0 + 2 + 144] = f2tf(fmaxf(acc[nt][3] + bb2b, 0.0f));
                            }
                        }
                    }
                }
                __syncthreads();

                // ---- layer 3 (R9 form) + lookahead L1 of tile 1 ----
                #pragma unroll
                for (int ng = 0; ng < 4; ng++) {
                    const int n0 = 32 * ng;
                    if (n0 >= tp) break;
                    const int ntmax = min(4, (tp - n0 + 7) >> 3);
                    float acc[4][4];
                    #pragma unroll
                    for (int nt = 0; nt < 4; nt++) {
                        acc[nt][0] = 0.f; acc[nt][1] = 0.f; acc[nt][2] = 0.f; acc[nt][3] = 0.f;
                    }
                    #pragma unroll
                    for (int sQ = 0; sQ < 8; sQ++) {
                        #pragma unroll
                        for (int nt = 0; nt < 4; nt++) {
                            if (nt < ntmax) {
                                const uint4 bQ = q4s[Q4_H2 + (n0 + 8 * nt + g) * H2Q + 4 * sQ + tq];
                                mma8(acc[nt][0], acc[nt][1], acc[nt][2], acc[nt][3],
                                     a3r[8 * sQ + 0], a3r[8 * sQ + 1], a3r[8 * sQ + 2], a3r[8 * sQ + 3],
                                     bQ.x, bQ.y);
                                mma8(acc[nt][0], acc[nt][1], acc[nt][2], acc[nt][3],
                                     a3r[8 * sQ + 4], a3r[8 * sQ + 5], a3r[8 * sQ + 6], a3r[8 * sQ + 7],
                                     bQ.z, bQ.w);
                            }
                        }
                    }
                    #pragma unroll
                    for (int nt = 0; nt < 4; nt++) {
                        const int p0 = n0 + 8 * nt + 2 * tq;
                        if (p0 < tp) {
                            chmax0 = fmaxf(chmax0, acc[nt][0]);
                            chmax1 = fmaxf(chmax1, acc[nt][2]);
                        }
                        if (p0 + 1 < tp) {
                            chmax0 = fmaxf(chmax0, acc[nt][1]);
                            chmax1 = fmaxf(chmax1, acc[nt][3]);
                        }
                    }
                }
                if (p0b + 128 < n) {
                    const int tpn = min(128, n - p0b - 128);
                    do_l1(cen0, cen1, cen2, is0, is1, is2, p0b + 128, (tpn + 7) & ~7);
                    __syncthreads();
                }
            }

            chmax0 = fmaxf(chmax0, __shfl_xor_sync(0xffffffffu, chmax0, 1));
            chmax0 = fmaxf(chmax0, __shfl_xor_sync(0xffffffffu, chmax0, 2));
            chmax1 = fmaxf(chmax1, __shfl_xor_sync(0xffffffffu, chmax1, 1));
            chmax1 = fmaxf(chmax1, __shfl_xor_sync(0xffffffffu, chmax1, 2));
            if (tq == 0) {
                s[OFF_FEATS + chw + g]     = chmax0 + bb3a;
                s[OFF_FEATS + chw + g + 8] = chmax1 + bb3b;
            }
        }

        __syncthreads();   // T1: feats ready; s_pid[par^1] published; H1 free
        const unsigned npid = s_pid[par ^ 1];

        // tail: heads (w<7) || prop/count staging (w==7) || point staging (w>=8)
        if (w < 7) {
            if (valid) {
                float acc = 0.0f;
                #pragma unroll
                for (int i = 0; i < 8; i++) {
                    const int idx = i * 32 + lane;
                    acc = fmaf(s[OFF_FEATS + idx], s[OFF_WH + w * 256 + idx], acc);
                }
                #pragma unroll
                for (int o = 16; o > 0; o >>= 1)
                    acc += __shfl_xor_sync(0xffffffffu, acc, o);
                if (lane == 0) {
                    if (w == 0) out[pid] = acc + s[OFF_BH];
                    else        out[NP + pid * 6 + (w - 1)] = acc + s[OFF_BH + w];
                }
            } else if (lane == 0) {
                if (w == 0) out[pid] = s[OFF_BH];
                else        out[NP + pid * 6 + (w - 1)] = s[OFF_BH + w];
            }
        } else if (w == 7) {
            if (npid < NP) {
                if (lane < 6) s_prop[lane] = proposals[(size_t)npid * 6 + lane];
                if (lane == 6) s_ncnt = counts[npid];
            }
        } else {
            if (npid < NP) {
                const int nn = counts[npid];
                const uint4* gp4 = (const uint4*)(points + (size_t)npid * (MAXNP * 3));
                uint4* sp4 = (uint4*)(s + OFF_PTS);
                const int nf4 = (3 * nn + 3) >> 2;
                for (int i = tid - 256; i < nf4; i += 256) sp4[i] = __ldg(gp4 + i);
            }
        }
        __syncthreads();   // T1.5: next points + prop + count staged

        // hidden L1: all warps compute next proposal's tile-0 H1
        if (npid < NP) {
            const int nn = s_ncnt;
            if (nn >= 4) {
                const float c0n = s_prop[0], c1n = s_prop[1], c2n = s_prop[2];
                const float i0n = 1.0f / (fabsf(s_prop[3]) + 1e-6f);
                const float i1n = 1.0f / (fabsf(s_prop[4]) + 1e-6f);
                const float i2n = 1.0f / (fabsf(s_prop[5]) + 1e-6f);
                const int tp0 = min(128, nn);
                do_l1(c0n, c1n, c2n, i0n, i1n, i2n, 0, (tp0 + 7) & ~7);
                h1_ready = true;
            } else {
                h1_ready = false;
            }
        } else {
            h1_ready = false;
        }
        __syncthreads();   // T2: H1(next) ready
        par ^= 1;
    }
}

extern "C" void kernel_launch(void* const* d_in, const int* in_sizes, int n_in,
                              void* d_out, int out_size)
{
    const float* points    = (const float*)d_in[0];
    const int*   counts    = (const int*)  d_in[1];
    const float* proposals = (const float*)d_in[2];
    const float* W1 = (const float*)d_in[3];
    const float* b1 = (const float*)d_in[4];
    const float* W2 = (const float*)d_in[5];
    const float* b2 = (const float*)d_in[6];
    const float* W3 = (const float*)d_in[7];
    const float* b3 = (const float*)d_in[8];
    const float* Wc = (const float*)d_in[9];
    const float* bc = (const float*)d_in[10];
    const float* Wr = (const float*)d_in[11];
    const float* br = (const float*)d_in[12];
    float* out = (float*)d_out;

    int dev = 0, sms = 148;
    cudaGetDevice(&dev);
    cudaDeviceGetAttribute(&sms, cudaDevAttrMultiProcessorCount, dev);
    cudaFuncSetAttribute(refine_kernel,
                         cudaFuncAttributeMaxDynamicSharedMemorySize,
                         SMEM_FLOATS * (int)sizeof(float));

    reset_ticket_kernel<<<1, 1>>>();
    refine_kernel<<<sms, 512, SMEM_FLOATS * (int)sizeof(float)>>>(
        points, counts, proposals, W1, b1, W2, b2, W3, b3, Wc, bc, Wr, br, out);
}

// round 14
// speedup vs baseline: 1.9716x; 1.3513x over previous
#include <cuda_runtime.h>
#include <cuda_fp16.h>
#include <math.h>
#include <float.h>

#define NP    2048
#define MAXNP 256

// ---- shared memory layout (float offsets unless noted) ----
#define Q4_H1   0            // u4 [0,2560): H1 tf32 quads, [128 pts][20 u4]
#define H1Q     20
#define Q4_W2   2560         // u4 [2560,5120): W2^T tf32 quads, [128 ch][20 u4]
#define W2Q     20
#define H2F     20480        // fp16 H2: 128 rows x 272B (byte off 81920), floats [20480,29184)
#define H2ROWH  136          // halfs per row
#define OFF_WH    29184      // 7*256
#define OFF_BH    30976      // 8
#define OFF_FEATS 30984      // 256
#define OFF_PTS   31240      // 768 floats, 16B aligned
#define OFF_STAT  32008      // S1, S2, b1max, b2max
#define OFF_WPM   32012      // 8 per-warp point abs-max
#define SMEM_FLOATS 32020    // 128,080 bytes

extern __shared__ float s[];

__device__ unsigned g_ticket;
__global__ void reset_ticket_kernel() { g_ticket = 0u; }

__device__ __forceinline__ unsigned f2tf(float f) {
    unsigned u; asm("cvt.rna.tf32.f32 %0, %1;" : "=r"(u) : "f"(f)); return u;
}
__device__ __forceinline__ unsigned pack_h2(float lo, float hi) {
    unsigned u; asm("cvt.rn.f16x2.f32 %0, %1, %2;" : "=r"(u) : "f"(hi), "f"(lo)); return u;
}
__device__ __forceinline__ unsigned smem_addr_u32(const void* p) {
    unsigned r;
    asm("{ .reg .u64 t; cvta.to.shared.u64 t, %1; cvt.u32.u64 %0, t; }" : "=r"(r) : "l"(p));
    return r;
}
__device__ __forceinline__ void mma8(float& c0, float& c1, float& c2, float& c3,
                                     unsigned a0, unsigned a1, unsigned a2, unsigned a3,
                                     unsigned b0, unsigned b1) {
    asm("mma.sync.aligned.m16n8k8.row.col.f32.tf32.tf32.f32 "
        "{%0,%1,%2,%3}, {%4,%5,%6,%7}, {%8,%9}, {%0,%1,%2,%3};"
        : "+f"(c0), "+f"(c1), "+f"(c2), "+f"(c3)
        : "r"(a0), "r"(a1), "r"(a2), "r"(a3), "r"(b0), "r"(b1));
}
__device__ __forceinline__ void mma16(float& c0, float& c1, float& c2, float& c3,
                                      unsigned a0, unsigned a1, unsigned a2, unsigned a3,
                                      unsigned b0, unsigned b1) {
    asm("mma.sync.aligned.m16n8k16.row.col.f32.f16.f16.f32 "
        "{%0,%1,%2,%3}, {%4,%5,%6,%7}, {%8,%9}, {%0,%1,%2,%3};"
        : "+f"(c0), "+f"(c1), "+f"(c2), "+f"(c3)
        : "r"(a0), "r"(a1), "r"(a2), "r"(a3), "r"(b0), "r"(b1));
}
__device__ __forceinline__ void ldsm4(unsigned& r0, unsigned& r1, unsigned& r2, unsigned& r3,
                                      unsigned addr) {
    asm volatile("ldmatrix.sync.aligned.m8n8.x4.shared.b16 {%0,%1,%2,%3}, [%4];"
                 : "=r"(r0), "=r"(r1), "=r"(r2), "=r"(r3) : "r"(addr));
}

__global__ __launch_bounds__(512, 1)
void refine_kernel(const float* __restrict__ points,
                   const int*   __restrict__ counts,
                   const float* __restrict__ proposals,
                   const float* __restrict__ W1, const float* __restrict__ b1,
                   const float* __restrict__ W2, const float* __restrict__ b2,
                   const float* __restrict__ W3, const float* __restrict__ b3,
                   const float* __restrict__ Wc, const float* __restrict__ bc,
                   const float* __restrict__ Wr, const float* __restrict__ br,
                   float* __restrict__ out)
{
    uint4*  q4s = (uint4*)s;
    __half* h2h = (__half*)(s + H2F);
    __shared__ unsigned s_pid[2];
    __shared__ float    s_prop[6];
    __shared__ int      s_ncnt;

    const int tid  = threadIdx.x;
    const int w    = tid >> 5;
    const int lane = tid & 31;
    const int g    = lane >> 2;
    const int tq   = lane & 3;
    const unsigned smem_u32 = smem_addr_u32(s);

    // ---- stage W2^T tf32 quads + head weights; stats partial pass (scratch in H1 region) ----
    for (int i = tid; i < 128 * 16; i += 512) {
        const int row = i >> 4, j = i & 15;
        const int sQ = j >> 2, tqQ = j & 3;
        const int k = 16 * sQ + tqQ;
        uint4 v;
        v.x = f2tf(W2[k * 128 + row]);
        v.y = f2tf(W2[(k + 4) * 128 + row]);
        v.z = f2tf(W2[(k + 8) * 128 + row]);
        v.w = f2tf(W2[(k + 12) * 128 + row]);
        q4s[Q4_W2 + row * W2Q + j] = v;
    }
    if (tid < 256) {
        s[OFF_WH + tid] = Wc[tid];
        #pragma unroll
        for (int j = 0; j < 6; j++) s[OFF_WH + (1 + j) * 256 + tid] = Wr[tid * 6 + j];
    }
    if (tid == 0) s[OFF_BH] = bc[0];
    if (tid >= 1 && tid < 7) s[OFF_BH + tid] = br[tid - 1];
    {   // |W2| column-sum partials: thread -> (col j, k-chunk c)
        const int j = tid & 127, c = tid >> 7;
        float pv = 0.0f;
        for (int k = 16 * c; k < 16 * c + 16; k++) pv += fabsf(W2[k * 128 + j]);
        s[tid] = pv;
    }
    __syncthreads();
    if (tid < 128) s[512 + tid] = s[tid] + s[128 + tid] + s[256 + tid] + s[384 + tid];
    if (tid >= 128 && tid < 192) {
        const int c = tid - 128;
        s[640 + c] = fabsf(W1[c]) + fabsf(W1[64 + c]) + fabsf(W1[128 + c]);
    }
    if (tid >= 192 && tid < 256) s[704 + (tid - 192)] = fabsf(b1[tid - 192]);
    if (tid >= 256 && tid < 384) s[768 + (tid - 256)] = fabsf(b2[tid - 256]);

    // ---- W3 fp16 A-fragments resident in registers (32 regs) ----
    const int chw = 16 * w;              // warp owns channels [16w, 16w+16)
    unsigned a3h[32];
    #pragma unroll
    for (int ks = 0; ks < 8; ks++) {
        const int k0 = 16 * ks;
        const int ca = chw + g, cb = chw + g + 8;
        a3h[4 * ks + 0] = pack_h2(W3[(k0 + 2 * tq) * 256 + ca], W3[(k0 + 2 * tq + 1) * 256 + ca]);
        a3h[4 * ks + 1] = pack_h2(W3[(k0 + 2 * tq) * 256 + cb], W3[(k0 + 2 * tq + 1) * 256 + cb]);
        a3h[4 * ks + 2] = pack_h2(W3[(k0 + 2 * tq + 8) * 256 + ca], W3[(k0 + 2 * tq + 9) * 256 + ca]);
        a3h[4 * ks + 3] = pack_h2(W3[(k0 + 2 * tq + 8) * 256 + cb], W3[(k0 + 2 * tq + 9) * 256 + cb]);
    }
    __syncthreads();
    if (tid == 0) {
        float S2 = 0, S1 = 0, b1m = 0, b2m = 0;
        for (int i = 0; i < 128; i++) S2 = fmaxf(S2, s[512 + i]);
        for (int i = 0; i < 64;  i++) S1 = fmaxf(S1, s[640 + i]);
        for (int i = 0; i < 64;  i++) b1m = fmaxf(b1m, s[704 + i]);
        for (int i = 0; i < 128; i++) b2m = fmaxf(b2m, s[768 + i]);
        s[OFF_STAT + 0] = S1; s[OFF_STAT + 1] = S2;
        s[OFF_STAT + 2] = b1m; s[OFF_STAT + 3] = b2m;
        s_pid[0] = atomicAdd(&g_ticket, 1u);
    }
    __syncthreads();

    const int wm  = w & 7;
    const int ch2 = 16 * wm + g;
    const float bb2a = b2[ch2];
    const float bb2b = b2[ch2 + 8];
    const float bb3a = b3[chw + g];
    const float bb3b = b3[chw + g + 8];
    const int l2half = w >> 3;
    // ldmatrix per-lane base (H2 fp16, 272B rows)
    const unsigned lmoff = smem_u32 + 81920u
        + (unsigned)((8 * (lane >> 4) + (lane & 7)) * 272 + ((lane >> 3) & 1) * 16);

    {   // prologue: stage first proposal (points by warps 8-15 with abs-max)
        const unsigned pid0 = s_pid[0];
        if (pid0 < NP) {
            if (tid == 0) s_ncnt = counts[pid0];
            if (tid >= 32 && tid < 38) s_prop[tid - 32] = proposals[pid0 * 6 + (tid - 32)];
            if (w >= 8) {
                const int nn = counts[pid0];
                const uint4* gp4 = (const uint4*)(points + (size_t)pid0 * (MAXNP * 3));
                uint4* sp4 = (uint4*)(s + OFF_PTS);
                const int nf4 = (3 * nn + 3) >> 2;
                float lm = 0.0f;
                for (int i = tid - 256; i < nf4; i += 256) {
                    const uint4 d = __ldg(gp4 + i);
                    sp4[i] = d;
                    lm = fmaxf(lm, fmaxf(fmaxf(fabsf(__uint_as_float(d.x)), fabsf(__uint_as_float(d.y))),
                                         fmaxf(fabsf(__uint_as_float(d.z)), fabsf(__uint_as_float(d.w)))));
                }
                #pragma unroll
                for (int o = 16; o > 0; o >>= 1) lm = fmaxf(lm, __shfl_xor_sync(0xffffffffu, lm, o));
                if (lane == 0) s[OFF_WPM + (w - 8)] = lm;
            }
        }
    }
    __syncthreads();

    auto do_l1 = [&](float cen0, float cen1, float cen2,
                     float is0, float is1, float is2, int base, int cnt8) {
        for (int i = tid; i < cnt8 * 16; i += 512) {
            const int p = i >> 4, j = i & 15;
            const int sQ = j >> 2, tqQ = j & 3;
            const int c = 16 * sQ + tqQ;
            const float* pt = s + OFF_PTS + (base + p) * 3;
            const float x0 = (pt[0] - cen0) * is0;
            const float x1 = (pt[1] - cen1) * is1;
            const float x2 = (pt[2] - cen2) * is2;
            uint4 v;
            { float h = fmaf(x2, W1[128 + c], fmaf(x1, W1[64 + c], fmaf(x0, W1[c], b1[c])));
              v.x = f2tf(fmaxf(h, 0.0f)); }
            { float h = fmaf(x2, W1[128 + c + 4], fmaf(x1, W1[64 + c + 4], fmaf(x0, W1[c + 4], b1[c + 4])));
              v.y = f2tf(fmaxf(h, 0.0f)); }
            { float h = fmaf(x2, W1[128 + c + 8], fmaf(x1, W1[64 + c + 8], fmaf(x0, W1[c + 8], b1[c + 8])));
              v.z = f2tf(fmaxf(h, 0.0f)); }
            { float h = fmaf(x2, W1[128 + c + 12], fmaf(x1, W1[64 + c + 12], fmaf(x0, W1[c + 12], b1[c + 12])));
              v.w = f2tf(fmaxf(h, 0.0f)); }
            q4s[Q4_H1 + p * H1Q + j] = v;
        }
    };

    int par = 0;
    for (;;) {
        const unsigned pid = s_pid[par];
        if (pid >= NP) break;
        if (tid == 0) s_pid[par ^ 1] = atomicAdd(&g_ticket, 1u);
        const int n = s_ncnt;
        const bool valid = (n >= 4);

        float chmax0 = -FLT_MAX, chmax1 = -FLT_MAX;
        float inv = 1.0f;

        if (valid) {
            const float cen0 = s_prop[0], cen1 = s_prop[1], cen2 = s_prop[2];
            const float is0 = 1.0f / (fabsf(s_prop[3]) + 1e-6f);
            const float is1 = 1.0f / (fabsf(s_prop[4]) + 1e-6f);
            const float is2 = 1.0f / (fabsf(s_prop[5]) + 1e-6f);

            // fp16 overflow guard: exact power-of-2 scale on H2
            float sc = 1.0f;
            {
                float ptm = s[OFF_WPM];
                #pragma unroll
                for (int i = 1; i < 8; i++) ptm = fmaxf(ptm, s[OFF_WPM + i]);
                const float cmax = fmaxf(fabsf(cen0), fmaxf(fabsf(cen1), fabsf(cen2)));
                const float ismax = fmaxf(is0, fmaxf(is1, is2));
                const float B1 = (ptm + cmax) * ismax * s[OFF_STAT] + s[OFF_STAT + 2];
                const float B2 = B1 * s[OFF_STAT + 1] + s[OFF_STAT + 3];
                if (B2 > 16384.0f) {
                    int e;
                    frexpf(B2 * (1.0f / 16384.0f), &e);
                    sc  = ldexpf(1.0f, -e);
                    inv = ldexpf(1.0f, e);
                }
            }

            { const int tp0 = min(128, n);
              do_l1(cen0, cen1, cen2, is0, is1, is2, 0, (tp0 + 7) & ~7); }
            __syncthreads();

            for (int p0b = 0; p0b < n; p0b += 128) {
                const int tp = min(128, n - p0b);

                // ---- layer 2 (tf32 mma) -> H2 fp16 (scaled) ----
                #pragma unroll
                for (int ng = 0; ng < 2; ng++) {
                    const int n0b = 64 * l2half + 32 * ng;
                    if (n0b < tp) {
                        const int ntmax = min(4, (tp - n0b + 7) >> 3);
                        float acc[4][4];
                        #pragma unroll
                        for (int nt = 0; nt < 4; nt++) {
                            acc[nt][0] = 0.f; acc[nt][1] = 0.f; acc[nt][2] = 0.f; acc[nt][3] = 0.f;
                        }
                        #pragma unroll
                        for (int sQ = 0; sQ < 4; sQ++) {
                            const uint4 aQ0 = q4s[Q4_W2 + (16 * wm + g)     * W2Q + 4 * sQ + tq];
                            const uint4 aQ1 = q4s[Q4_W2 + (16 * wm + g + 8) * W2Q + 4 * sQ + tq];
                            #pragma unroll
                            for (int nt = 0; nt < 4; nt++) {
                                if (nt < ntmax) {
                                    const uint4 bQ = q4s[Q4_H1 + (n0b + 8 * nt + g) * H1Q + 4 * sQ + tq];
                                    mma8(acc[nt][0], acc[nt][1], acc[nt][2], acc[nt][3],
                                         aQ0.x, aQ1.x, aQ0.y, aQ1.y, bQ.x, bQ.y);
                                    mma8(acc[nt][0], acc[nt][1], acc[nt][2], acc[nt][3],
                                         aQ0.z, aQ1.z, aQ0.w, aQ1.w, bQ.z, bQ.w);
                                }
                            }
                        }
                        #pragma unroll
                        for (int nt = 0; nt < 4; nt++) {
                            if (nt < ntmax) {
                                const int p0 = n0b + 8 * nt + 2 * tq;
                                __half* r0 = h2h + p0 * H2ROWH;
                                __half* r1 = r0 + H2ROWH;
                                r0[ch2]     = __float2half(fmaxf(acc[nt][0] + bb2a, 0.0f) * sc);
                                r1[ch2]     = __float2half(fmaxf(acc[nt][1] + bb2a, 0.0f) * sc);
                                r0[ch2 + 8] = __float2half(fmaxf(acc[nt][2] + bb2b, 0.0f) * sc);
                                r1[ch2 + 8] = __float2half(fmaxf(acc[nt][3] + bb2b, 0.0f) * sc);
                            }
                        }
                    }
                }
                __syncthreads();

                // ---- layer 3: fp16 m16n8k16, B via ldmatrix.x4 ----
                #pragma unroll
                for (int ng = 0; ng < 4; ng++) {
                    const int n0 = 32 * ng;
                    if (n0 >= tp) break;
                    const int ntmax = min(4, (tp - n0 + 7) >> 3);
                    float acc[4][4];
                    #pragma unroll
                    for (int nt = 0; nt < 4; nt++) {
                        acc[nt][0] = 0.f; acc[nt][1] = 0.f; acc[nt][2] = 0.f; acc[nt][3] = 0.f;
                    }
                    const unsigned ngbase = lmoff + (unsigned)(n0 * 272);
                    #pragma unroll
                    for (int ks = 0; ks < 8; ks++) {
                        unsigned lm0, lm1, lm2, lm3, lm4, lm5, lm6, lm7;
                        ldsm4(lm0, lm1, lm2, lm3, ngbase + 32u * ks);
                        if (ntmax > 2)
                            ldsm4(lm4, lm5, lm6, lm7, ngbase + 32u * ks + 16u * 272u);
                        mma16(acc[0][0], acc[0][1], acc[0][2], acc[0][3],
                              a3h[4 * ks + 0], a3h[4 * ks + 1], a3h[4 * ks + 2], a3h[4 * ks + 3],
                              lm0, lm1);
                        if (ntmax > 1)
                            mma16(acc[1][0], acc[1][1], acc[1][2], acc[1][3],
                                  a3h[4 * ks + 0], a3h[4 * ks + 1], a3h[4 * ks + 2], a3h[4 * ks + 3],
                                  lm2, lm3);
                        if (ntmax > 2)
                            mma16(acc[2][0], acc[2][1], acc[2][2], acc[2][3],
                                  a3h[4 * ks + 0], a3h[4 * ks + 1], a3h[4 * ks + 2], a3h[4 * ks + 3],
                                  lm4, lm5);
                        if (ntmax > 3)
                            mma16(acc[3][0], acc[3][1], acc[3][2], acc[3][3],
                                  a3h[4 * ks + 0], a3h[4 * ks + 1], a3h[4 * ks + 2], a3h[4 * ks + 3],
                                  lm6, lm7);
                    }
                    #pragma unroll
                    for (int nt = 0; nt < 4; nt++) {
                        const int p0 = n0 + 8 * nt + 2 * tq;
                        if (p0 < tp) {
                            chmax0 = fmaxf(chmax0, acc[nt][0]);
                            chmax1 = fmaxf(chmax1, acc[nt][2]);
                        }
                        if (p0 + 1 < tp) {
                            chmax0 = fmaxf(chmax0, acc[nt][1]);
                            chmax1 = fmaxf(chmax1, acc[nt][3]);
                        }
                    }
                }
                if (p0b + 128 < n) {
                    const int tpn = min(128, n - p0b - 128);
                    do_l1(cen0, cen1, cen2, is0, is1, is2, p0b + 128, (tpn + 7) & ~7);
                    __syncthreads();
                }
            }

            chmax0 = fmaxf(chmax0, __shfl_xor_sync(0xffffffffu, chmax0, 1));
            chmax0 = fmaxf(chmax0, __shfl_xor_sync(0xffffffffu, chmax0, 2));
            chmax1 = fmaxf(chmax1, __shfl_xor_sync(0xffffffffu, chmax1, 1));
            chmax1 = fmaxf(chmax1, __shfl_xor_sync(0xffffffffu, chmax1, 2));
            if (tq == 0) {
                s[OFF_FEATS + chw + g]     = chmax0 * inv + bb3a;
                s[OFF_FEATS + chw + g + 8] = chmax1 * inv + bb3b;
            }
        }

        __syncthreads();   // T1: feats ready; s_pid[par^1] published; buffers free
        const unsigned npid = s_pid[par ^ 1];

        if (w < 7) {
            if (valid) {
                float acc = 0.0f;
                #pragma unroll
                for (int i = 0; i < 8; i++) {
                    const int idx = i * 32 + lane;
                    acc = fmaf(s[OFF_FEATS + idx], s[OFF_WH + w * 256 + idx], acc);
                }
                #pragma unroll
                for (int o = 16; o > 0; o >>= 1)
                    acc += __shfl_xor_sync(0xffffffffu, acc, o);
                if (lane == 0) {
                    if (w == 0) out[pid] = acc + s[OFF_BH];
                    else        out[NP + pid * 6 + (w - 1)] = acc + s[OFF_BH + w];
                }
            } else if (lane == 0) {
                if (w == 0) out[pid] = s[OFF_BH];
                else        out[NP + pid * 6 + (w - 1)] = s[OFF_BH + w];
            }
        } else if (w == 7) {
            if (npid < NP) {
                if (lane < 6) s_prop[lane] = proposals[(size_t)npid * 6 + lane];
                if (lane == 6) s_ncnt = counts[npid];
            }
        } else {
            if (npid < NP) {
                const int nn = counts[npid];
                const uint4* gp4 = (const uint4*)(points + (size_t)npid * (MAXNP * 3));
                uint4* sp4 = (uint4*)(s + OFF_PTS);
                const int nf4 = (3 * nn + 3) >> 2;
                float lm = 0.0f;
                for (int i = tid - 256; i < nf4; i += 256) {
                    const uint4 d = __ldg(gp4 + i);
                    sp4[i] = d;
                    lm = fmaxf(lm, fmaxf(fmaxf(fabsf(__uint_as_float(d.x)), fabsf(__uint_as_float(d.y))),
                                         fmaxf(fabsf(__uint_as_float(d.z)), fabsf(__uint_as_float(d.w)))));
                }
                #pragma unroll
                for (int o = 16; o > 0; o >>= 1) lm = fmaxf(lm, __shfl_xor_sync(0xffffffffu, lm, o));
                if (lane == 0) s[OFF_WPM + (w - 8)] = lm;
            }
        }
        __syncthreads();   // T2: next proposal staged
        par ^= 1;
    }
}

extern "C" void kernel_launch(void* const* d_in, const int* in_sizes, int n_in,
                              void* d_out, int out_size)
{
    const float* points    = (const float*)d_in[0];
    const int*   counts    = (const int*)  d_in[1];
    const float* proposals = (const float*)d_in[2];
    const float* W1 = (const float*)d_in[3];
    const float* b1 = (const float*)d_in[4];
    const float* W2 = (const float*)d_in[5];
    const float* b2 = (const float*)d_in[6];
    const float* W3 = (const float*)d_in[7];
    const float* b3 = (const float*)d_in[8];
    const float* Wc = (const float*)d_in[9];
    const float* bc = (const float*)d_in[10];
    const float* Wr = (const float*)d_in[11];
    const float* br = (const float*)d_in[12];
    float* out = (float*)d_out;

    int dev = 0, sms = 148;
    cudaGetDevice(&dev);
    cudaDeviceGetAttribute(&sms, cudaDevAttrMultiProcessorCount, dev);
    cudaFuncSetAttribute(refine_kernel,
                         cudaFuncAttributeMaxDynamicSharedMemorySize,
                         SMEM_FLOATS * (int)sizeof(float));

    reset_ticket_kernel<<<1, 1>>>();
    refine_kernel<<<sms, 512, SMEM_FLOATS * (int)sizeof(float)>>>(
        points, counts, proposals, W1, b1, W2, b2, W3, b3, Wc, bc, Wr, br, out);
}

// round 16
// speedup vs baseline: 2.2435x; 1.1379x over previous
#include <cuda_runtime.h>
#include <cuda_fp16.h>
#include <math.h>
#include <float.h>

#define NP    2048
#define MAXNP 256

// ---- shared memory layout (float offsets) ----
#define H1F     0            // fp16 H1: 128 rows x 144B (72 halfs) = 4608 floats
#define H1ROWH  72
#define H2F     4608         // fp16 H2: 128 rows x 272B (136 halfs) = 8704 floats
#define H2ROWH  136
#define OFF_WH    13312      // 7*256
#define OFF_BH    15104      // 8
#define OFF_FEATS 15112      // 256
#define OFF_PTS   15368      // 768 floats, 16B aligned
#define OFF_STAT  16136      // S1, S2, b1max, b2max
#define OFF_WPM   16140      // 8 per-warp point abs-max
#define SMEM_FLOATS 16152    // 64,608 bytes

extern __shared__ float s[];

__device__ unsigned g_ticket;
__global__ void reset_ticket_kernel() { g_ticket = 0u; }

__device__ __forceinline__ unsigned pack_h2(float lo, float hi) {
    unsigned u; asm("cvt.rn.f16x2.f32 %0, %1, %2;" : "=r"(u) : "f"(hi), "f"(lo)); return u;
}
__device__ __forceinline__ unsigned smem_addr_u32(const void* p) {
    unsigned r;
    asm("{ .reg .u64 t; cvta.to.shared.u64 t, %1; cvt.u32.u64 %0, t; }" : "=r"(r) : "l"(p));
    return r;
}
__device__ __forceinline__ void mma16(float& c0, float& c1, float& c2, float& c3,
                                      unsigned a0, unsigned a1, unsigned a2, unsigned a3,
                                      unsigned b0, unsigned b1) {
    asm("mma.sync.aligned.m16n8k16.row.col.f32.f16.f16.f32 "
        "{%0,%1,%2,%3}, {%4,%5,%6,%7}, {%8,%9}, {%0,%1,%2,%3};"
        : "+f"(c0), "+f"(c1), "+f"(c2), "+f"(c3)
        : "r"(a0), "r"(a1), "r"(a2), "r"(a3), "r"(b0), "r"(b1));
}
__device__ __forceinline__ void ldsm4(unsigned& r0, unsigned& r1, unsigned& r2, unsigned& r3,
                                      unsigned addr) {
    asm volatile("ldmatrix.sync.aligned.m8n8.x4.shared.b16 {%0,%1,%2,%3}, [%4];"
                 : "=r"(r0), "=r"(r1), "=r"(r2), "=r"(r3) : "r"(addr));
}

__global__ __launch_bounds__(512, 1)
void refine_kernel(const float* __restrict__ points,
                   const int*   __restrict__ counts,
                   const float* __restrict__ proposals,
                   const float* __restrict__ W1, const float* __restrict__ b1,
                   const float* __restrict__ W2, const float* __restrict__ b2,
                   const float* __restrict__ W3, const float* __restrict__ b3,
                   const float* __restrict__ Wc, const float* __restrict__ bc,
                   const float* __restrict__ Wr, const float* __restrict__ br,
                   float* __restrict__ out)
{
    __half* h1h = (__half*)(s + H1F);
    __half* h2h = (__half*)(s + H2F);
    __shared__ unsigned s_pid[2];
    __shared__ float    s_prop[6];
    __shared__ int      s_ncnt;

    const int tid  = threadIdx.x;
    const int w    = tid >> 5;
    const int lane = tid & 31;
    const int g    = lane >> 2;
    const int tq   = lane & 3;
    const unsigned smem_u32 = smem_addr_u32(s);

    // ---- head weights/biases ----
    if (tid < 256) {
        s[OFF_WH + tid] = Wc[tid];
        #pragma unroll
        for (int j = 0; j < 6; j++) s[OFF_WH + (1 + j) * 256 + tid] = Wr[tid * 6 + j];
    }
    if (tid == 0) s[OFF_BH] = bc[0];
    if (tid >= 1 && tid < 7) s[OFF_BH + tid] = br[tid - 1];
    {   // |W2| column-sum partials in H1 scratch (free until first L1)
        const int j = tid & 127, c = tid >> 7;
        float pv = 0.0f;
        for (int k = 16 * c; k < 16 * c + 16; k++) pv += fabsf(W2[k * 128 + j]);
        s[tid] = pv;
    }
    __syncthreads();
    if (tid < 128) s[512 + tid] = s[tid] + s[128 + tid] + s[256 + tid] + s[384 + tid];
    if (tid >= 128 && tid < 192) {
        const int c = tid - 128;
        s[640 + c] = fabsf(W1[c]) + fabsf(W1[64 + c]) + fabsf(W1[128 + c]);
    }
    if (tid >= 192 && tid < 256) s[704 + (tid - 192)] = fabsf(b1[tid - 192]);
    if (tid >= 256 && tid < 384) s[768 + (tid - 256)] = fabsf(b2[tid - 256]);

    // ---- W3 fp16 A-fragments (32 regs): warp owns channels [16w, 16w+16) ----
    const int chw = 16 * w;
    unsigned a3h[32];
    #pragma unroll
    for (int ks = 0; ks < 8; ks++) {
        const int k0 = 16 * ks;
        const int ca = chw + g, cb = chw + g + 8;
        a3h[4 * ks + 0] = pack_h2(W3[(k0 + 2 * tq) * 256 + ca], W3[(k0 + 2 * tq + 1) * 256 + ca]);
        a3h[4 * ks + 1] = pack_h2(W3[(k0 + 2 * tq) * 256 + cb], W3[(k0 + 2 * tq + 1) * 256 + cb]);
        a3h[4 * ks + 2] = pack_h2(W3[(k0 + 2 * tq + 8) * 256 + ca], W3[(k0 + 2 * tq + 9) * 256 + ca]);
        a3h[4 * ks + 3] = pack_h2(W3[(k0 + 2 * tq + 8) * 256 + cb], W3[(k0 + 2 * tq + 9) * 256 + cb]);
    }
    // ---- W2 fp16 A-fragments (16 regs): layer-2 warp wm owns channels [16wm, +16) ----
    const int wm  = w & 7;
    const int ch2 = 16 * wm + g;
    unsigned a2h[16];
    #pragma unroll
    for (int ks = 0; ks < 4; ks++) {
        const int k0 = 16 * ks;
        a2h[4 * ks + 0] = pack_h2(W2[(k0 + 2 * tq) * 128 + ch2], W2[(k0 + 2 * tq + 1) * 128 + ch2]);
        a2h[4 * ks + 1] = pack_h2(W2[(k0 + 2 * tq) * 128 + ch2 + 8], W2[(k0 + 2 * tq + 1) * 128 + ch2 + 8]);
        a2h[4 * ks + 2] = pack_h2(W2[(k0 + 2 * tq + 8) * 128 + ch2], W2[(k0 + 2 * tq + 9) * 128 + ch2]);
        a2h[4 * ks + 3] = pack_h2(W2[(k0 + 2 * tq + 8) * 128 + ch2 + 8], W2[(k0 + 2 * tq + 9) * 128 + ch2 + 8]);
    }
    __syncthreads();
    if (tid == 0) {
        float S2 = 0, S1 = 0, b1m = 0, b2m = 0;
        for (int i = 0; i < 128; i++) S2 = fmaxf(S2, s[512 + i]);
        for (int i = 0; i < 64;  i++) S1 = fmaxf(S1, s[640 + i]);
        for (int i = 0; i < 64;  i++) b1m = fmaxf(b1m, s[704 + i]);
        for (int i = 0; i < 128; i++) b2m = fmaxf(b2m, s[768 + i]);
        s[OFF_STAT + 0] = S1; s[OFF_STAT + 1] = S2;
        s[OFF_STAT + 2] = b1m; s[OFF_STAT + 3] = b2m;
        s_pid[0] = atomicAdd(&g_ticket, 1u);
    }
    __syncthreads();

    const float bb2a = b2[ch2];
    const float bb2b = b2[ch2 + 8];
    const float bb3a = b3[chw + g];
    const float bb3b = b3[chw + g + 8];
    const int l2half = w >> 3;
    // ldmatrix per-lane bases: row-within-16 = 8*(lane>>4)+(lane&7), chunk = (lane>>3)&1
    const int lrow = 8 * (lane >> 4) + (lane & 7);
    const unsigned lm3off = smem_u32 + (unsigned)(H2F * 4) + (unsigned)(lrow * 272 + ((lane >> 3) & 1) * 16);
    const unsigned lm2off = smem_u32 + (unsigned)(lrow * 144 + ((lane >> 3) & 1) * 16);

    {   // prologue: stage first proposal (points by warps 8-15 with abs-max)
        const unsigned pid0 = s_pid[0];
        if (pid0 < NP) {
            if (tid == 0) s_ncnt = counts[pid0];
            if (tid >= 32 && tid < 38) s_prop[tid - 32] = proposals[pid0 * 6 + (tid - 32)];
            if (w >= 8) {
                const int nn = counts[pid0];
                const uint4* gp4 = (const uint4*)(points + (size_t)pid0 * (MAXNP * 3));
                uint4* sp4 = (uint4*)(s + OFF_PTS);
                const int nf4 = (3 * nn + 3) >> 2;
                float lm = 0.0f;
                for (int i = tid - 256; i < nf4; i += 256) {
                    const uint4 d = __ldg(gp4 + i);
                    sp4[i] = d;
                    lm = fmaxf(lm, fmaxf(fmaxf(fabsf(__uint_as_float(d.x)), fabsf(__uint_as_float(d.y))),
                                         fmaxf(fabsf(__uint_as_float(d.z)), fabsf(__uint_as_float(d.w)))));
                }
                #pragma unroll
                for (int o = 16; o > 0; o >>= 1) lm = fmaxf(lm, __shfl_xor_sync(0xffffffffu, lm, o));
                if (lane == 0) s[OFF_WPM + (w - 8)] = lm;
            }
        }
    }
    __syncthreads();

    // layer-1: fp16 H1 rows (channels in natural order), scaled by sc1
    auto do_l1 = [&](float cen0, float cen1, float cen2,
                     float is0, float is1, float is2, float sc1, int base, int cnt8) {
        for (int i = tid; i < cnt8 * 16; i += 512) {
            const int p = i >> 4, j = i & 15;
            const int c = 4 * j;
            const float* pt = s + OFF_PTS + (base + p) * 3;
            const float x0 = (pt[0] - cen0) * is0;
            const float x1 = (pt[1] - cen1) * is1;
            const float x2 = (pt[2] - cen2) * is2;
            float h0 = fmaf(x2, W1[128 + c],     fmaf(x1, W1[64 + c],     fmaf(x0, W1[c],     b1[c])));
            float h1v = fmaf(x2, W1[128 + c + 1], fmaf(x1, W1[64 + c + 1], fmaf(x0, W1[c + 1], b1[c + 1])));
            float h2v = fmaf(x2, W1[128 + c + 2], fmaf(x1, W1[64 + c + 2], fmaf(x0, W1[c + 2], b1[c + 2])));
            float h3v = fmaf(x2, W1[128 + c + 3], fmaf(x1, W1[64 + c + 3], fmaf(x0, W1[c + 3], b1[c + 3])));
            uint2 v;
            v.x = pack_h2(fmaxf(h0, 0.0f) * sc1, fmaxf(h1v, 0.0f) * sc1);
            v.y = pack_h2(fmaxf(h2v, 0.0f) * sc1, fmaxf(h3v, 0.0f) * sc1);
            *(uint2*)(h1h + p * H1ROWH + c) = v;
        }
    };

    int par = 0;
    for (;;) {
        const unsigned pid = s_pid[par];
        if (pid >= NP) break;
        if (tid == 0) s_pid[par ^ 1] = atomicAdd(&g_ticket, 1u);
        const int n = s_ncnt;
        const bool valid = (n >= 4);

        float chmax0 = -FLT_MAX, chmax1 = -FLT_MAX;
        float inv2 = 1.0f;

        if (valid) {
            const float cen0 = s_prop[0], cen1 = s_prop[1], cen2 = s_prop[2];
            const float is0 = 1.0f / (fabsf(s_prop[3]) + 1e-6f);
            const float is1 = 1.0f / (fabsf(s_prop[4]) + 1e-6f);
            const float is2 = 1.0f / (fabsf(s_prop[5]) + 1e-6f);

            // fp16 overflow guards: exact power-of-2 scales for H1 and H2
            float sc1 = 1.0f, inv1 = 1.0f, sc2 = 1.0f;
            {
                float ptm = s[OFF_WPM];
                #pragma unroll
                for (int i = 1; i < 8; i++) ptm = fmaxf(ptm, s[OFF_WPM + i]);
                const float cmax = fmaxf(fabsf(cen0), fmaxf(fabsf(cen1), fabsf(cen2)));
                const float ismax = fmaxf(is0, fmaxf(is1, is2));
                const float B1 = (ptm + cmax) * ismax * s[OFF_STAT] + s[OFF_STAT + 2];
                const float B2 = B1 * s[OFF_STAT + 1] + s[OFF_STAT + 3];
                if (B1 > 16384.0f) {
                    int e; frexpf(B1 * (1.0f / 16384.0f), &e);
                    sc1 = ldexpf(1.0f, -e); inv1 = ldexpf(1.0f, e);
                }
                if (B2 > 16384.0f) {
                    int e; frexpf(B2 * (1.0f / 16384.0f), &e);
                    sc2 = ldexpf(1.0f, -e); inv2 = ldexpf(1.0f, e);
                }
            }

            { const int tp0 = min(128, n);
              do_l1(cen0, cen1, cen2, is0, is1, is2, sc1, 0, (tp0 + 7) & ~7); }
            __syncthreads();

            for (int p0b = 0; p0b < n; p0b += 128) {
                const int tp = min(128, n - p0b);

                // ---- layer 2: fp16 m16n8k16, A=W2 regs, B=H1 via ldmatrix ----
                #pragma unroll
                for (int ng = 0; ng < 2; ng++) {
                    const int n0b = 64 * l2half + 32 * ng;
                    if (n0b < tp) {
                        const int ntmax = min(4, (tp - n0b + 7) >> 3);
                        float acc[4][4];
                        #pragma unroll
                        for (int nt = 0; nt < 4; nt++) {
                            acc[nt][0] = 0.f; acc[nt][1] = 0.f; acc[nt][2] = 0.f; acc[nt][3] = 0.f;
                        }
                        const unsigned b2base = lm2off + (unsigned)(n0b * 144);
                        #pragma unroll
                        for (int ks = 0; ks < 4; ks++) {
                            unsigned m0, m1, m2, m3, m4, m5, m6, m7;
                            ldsm4(m0, m1, m2, m3, b2base + 32u * ks);
                            if (ntmax > 2)
                                ldsm4(m4, m5, m6, m7, b2base + 32u * ks + 16u * 144u);
                            mma16(acc[0][0], acc[0][1], acc[0][2], acc[0][3],
                                  a2h[4 * ks + 0], a2h[4 * ks + 1], a2h[4 * ks + 2], a2h[4 * ks + 3],
                                  m0, m1);
                            if (ntmax > 1)
                                mma16(acc[1][0], acc[1][1], acc[1][2], acc[1][3],
                                      a2h[4 * ks + 0], a2h[4 * ks + 1], a2h[4 * ks + 2], a2h[4 * ks + 3],
                                      m2, m3);
                            if (ntmax > 2)
                                mma16(acc[2][0], acc[2][1], acc[2][2], acc[2][3],
                                      a2h[4 * ks + 0], a2h[4 * ks + 1], a2h[4 * ks + 2], a2h[4 * ks + 3],
                                      m4, m5);
                            if (ntmax > 3)
                                mma16(acc[3][0], acc[3][1], acc[3][2], acc[3][3],
                                      a2h[4 * ks + 0], a2h[4 * ks + 1], a2h[4 * ks + 2], a2h[4 * ks + 3],
                                      m6, m7);
                        }
                        #pragma unroll
                        for (int nt = 0; nt < 4; nt++) {
                            if (nt < ntmax) {
                                const int p0 = n0b + 8 * nt + 2 * tq;
                                __half* r0 = h2h + p0 * H2ROWH;
                                __half* r1 = r0 + H2ROWH;
                                r0[ch2]     = __float2half(fmaxf(fmaf(acc[nt][0], inv1, bb2a), 0.0f) * sc2);
                                r1[ch2]     = __float2half(fmaxf(fmaf(acc[nt][1], inv1, bb2a), 0.0f) * sc2);
                                r0[ch2 + 8] = __float2half(fmaxf(fmaf(acc[nt][2], inv1, bb2b), 0.0f) * sc2);
                                r1[ch2 + 8] = __float2half(fmaxf(fmaf(acc[nt][3], inv1, bb2b), 0.0f) * sc2);
                            }
                        }
                    }
                }
                __syncthreads();

                // ---- layer 3: fp16 m16n8k16, B via ldmatrix ----
                #pragma unroll
                for (int ng = 0; ng < 4; ng++) {
                    const int n0 = 32 * ng;
                    if (n0 >= tp) break;
                    const int ntmax = min(4, (tp - n0 + 7) >> 3);
                    float acc[4][4];
                    #pragma unroll
                    for (int nt = 0; nt < 4; nt++) {
                        acc[nt][0] = 0.f; acc[nt][1] = 0.f; acc[nt][2] = 0.f; acc[nt][3] = 0.f;
                    }
                    const unsigned b3base = lm3off + (unsigned)(n0 * 272);
                    #pragma unroll
                    for (int ks = 0; ks < 8; ks++) {
                        unsigned m0, m1, m2, m3, m4, m5, m6, m7;
                        ldsm4(m0, m1, m2, m3, b3base + 32u * ks);
                        if (ntmax > 2)
                            ldsm4(m4, m5, m6, m7, b3base + 32u * ks + 16u * 272u);
                        mma16(acc[0][0], acc[0][1], acc[0][2], acc[0][3],
                              a3h[4 * ks + 0], a3h[4 * ks + 1], a3h[4 * ks + 2], a3h[4 * ks + 3],
                              m0, m1);
                        if (ntmax > 1)
                            mma16(acc[1][0], acc[1][1], acc[1][2], acc[1][3],
                                  a3h[4 * ks + 0], a3h[4 * ks + 1], a3h[4 * ks + 2], a3h[4 * ks + 3],
                                  m2, m3);
                        if (ntmax > 2)
                            mma16(acc[2][0], acc[2][1], acc[2][2], acc[2][3],
                                  a3h[4 * ks + 0], a3h[4 * ks + 1], a3h[4 * ks + 2], a3h[4 * ks + 3],
                                  m4, m5);
                        if (ntmax > 3)
                            mma16(acc[3][0], acc[3][1], acc[3][2], acc[3][3],
                                  a3h[4 * ks + 0], a3h[4 * ks + 1], a3h[4 * ks + 2], a3h[4 * ks + 3],
                                  m6, m7);
                    }
                    #pragma unroll
                    for (int nt = 0; nt < 4; nt++) {
                        const int p0 = n0 + 8 * nt + 2 * tq;
                        if (p0 < tp) {
                            chmax0 = fmaxf(chmax0, acc[nt][0]);
                            chmax1 = fmaxf(chmax1, acc[nt][2]);
                        }
                        if (p0 + 1 < tp) {
                            chmax0 = fmaxf(chmax0, acc[nt][1]);
                            chmax1 = fmaxf(chmax1, acc[nt][3]);
                        }
                    }
                }
                if (p0b + 128 < n) {
                    const int tpn = min(128, n - p0b - 128);
                    do_l1(cen0, cen1, cen2, is0, is1, is2, sc1, p0b + 128, (tpn + 7) & ~7);
                    __syncthreads();
                }
            }

            chmax0 = fmaxf(chmax0, __shfl_xor_sync(0xffffffffu, chmax0, 1));
            chmax0 = fmaxf(chmax0, __shfl_xor_sync(0xffffffffu, chmax0, 2));
            chmax1 = fmaxf(chmax1, __shfl_xor_sync(0xffffffffu, chmax1, 1));
            chmax1 = fmaxf(chmax1, __shfl_xor_sync(0xffffffffu, chmax1, 2));
            if (tq == 0) {
                s[OFF_FEATS + chw + g]     = chmax0 * inv2 + bb3a;
                s[OFF_FEATS + chw + g + 8] = chmax1 * inv2 + bb3b;
            }
        }

        __syncthreads();   // T1: feats ready; s_pid[par^1] published; buffers free
        const unsigned npid = s_pid[par ^ 1];

        if (w < 7) {
            if (valid) {
                float acc = 0.0f;
                #pragma unroll
                for (int i = 0; i < 8; i++) {
                    const int idx = i * 32 + lane;
                    acc = fmaf(s[OFF_FEATS + idx], s[OFF_WH + w * 256 + idx], acc);
                }
                #pragma unroll
                for (int o = 16; o > 0; o >>= 1)
                    acc += __shfl_xor_sync(0xffffffffu, acc, o);
                if (lane == 0) {
                    if (w == 0) out[pid] = acc + s[OFF_BH];
                    else        out[NP + pid * 6 + (w - 1)] = acc + s[OFF_BH + w];
                }
            } else if (lane == 0) {
                if (w == 0) out[pid] = s[OFF_BH];
                else        out[NP + pid * 6 + (w - 1)] = s[OFF_BH + w];
            }
        } else if (w == 7) {
            if (npid < NP) {
                if (lane < 6) s_prop[lane] = proposals[(size_t)npid * 6 + lane];
                if (lane == 6) s_ncnt = counts[npid];
            }
        } else {
            if (npid < NP) {
                const int nn = counts[npid];
                const uint4* gp4 = (const uint4*)(points + (size_t)npid * (MAXNP * 3));
                uint4* sp4 = (uint4*)(s + OFF_PTS);
                const int nf4 = (3 * nn + 3) >> 2;
                float lm = 0.0f;
                for (int i = tid - 256; i < nf4; i += 256) {
                    const uint4 d = __ldg(gp4 + i);
                    sp4[i] = d;
                    lm = fmaxf(lm, fmaxf(fmaxf(fabsf(__uint_as_float(d.x)), fabsf(__uint_as_float(d.y))),
                                         fmaxf(fabsf(__uint_as_float(d.z)), fabsf(__uint_as_float(d.w)))));
                }
                #pragma unroll
                for (int o = 16; o > 0; o >>= 1) lm = fmaxf(lm, __shfl_xor_sync(0xffffffffu, lm, o));
                if (lane == 0) s[OFF_WPM + (w - 8)] = lm;
            }
        }
        __syncthreads();   // T2: next proposal staged
        par ^= 1;
    }
}

extern "C" void kernel_launch(void* const* d_in, const int* in_sizes, int n_in,
                              void* d_out, int out_size)
{
    const float* points    = (const float*)d_in[0];
    const int*   counts    = (const int*)  d_in[1];
    const float* proposals = (const float*)d_in[2];
    const float* W1 = (const float*)d_in[3];
    const float* b1 = (const float*)d_in[4];
    const float* W2 = (const float*)d_in[5];
    const float* b2 = (const float*)d_in[6];
    const float* W3 = (const float*)d_in[7];
    const float* b3 = (const float*)d_in[8];
    const float* Wc = (const float*)d_in[9];
    const float* bc = (const float*)d_in[10];
    const float* Wr = (const float*)d_in[11];
    const float* br = (const float*)d_in[12];
    float* out = (float*)d_out;

    int dev = 0, sms = 148;
    cudaGetDevice(&dev);
    cudaDeviceGetAttribute(&sms, cudaDevAttrMultiProcessorCount, dev);
    cudaFuncSetAttribute(refine_kernel,
                         cudaFuncAttributeMaxDynamicSharedMemorySize,
                         SMEM_FLOATS * (int)sizeof(float));

    reset_ticket_kernel<<<1, 1>>>();
    refine_kernel<<<sms, 512, SMEM_FLOATS * (int)sizeof(float)>>>(
        points, counts, proposals, W1, b1, W2, b2, W3, b3, Wc, bc, Wr, br, out);
}